// round 4
// baseline (speedup 1.0000x reference)
#include <cuda_runtime.h>
#include <math.h>
#include <float.h>

// Problem constants (fixed by dataset)
#define C_DIM   300
#define A_DIM   32
#define XSTR    600            // X row = [options(300) | cards(300)]
#define CP_PAD  152            // c-pairs (150 real, 2 zero-padded for tail)
#define C_PAD   306            // Wt row pad
#define APT_PAD 12             // apt row pad: 48B => 16B aligned float4 rows
#define WARPS   8
#define RPW     8              // rows per warp
#define RPB     (WARPS*RPW)    // 64 rows per block

// smem floats: Wp = CP_PAD*32 u64 = CP_PAD*64 floats; Wt = 32*306; apt = 8*32*12
#define WP_FLOATS   (CP_PAD*64)
#define SMEM_FLOATS (WP_FLOATS + A_DIM*C_PAD + WARPS*A_DIM*APT_PAD)
#define SMEM_BYTES  (SMEM_FLOATS * 4)

typedef unsigned long long u64;

// ---- packed f32x2 helpers (Blackwell FFMA2 path; only reachable via PTX) ----
__device__ __forceinline__ u64 pack2(float x, float y) {
    u64 r; asm("mov.b64 %0, {%1,%2};" : "=l"(r) : "f"(x), "f"(y)); return r;
}
__device__ __forceinline__ u64 dup2(float x) { return pack2(x, x); }
__device__ __forceinline__ void unpack2(u64 p, float &x, float &y) {
    asm("mov.b64 {%0,%1}, %2;" : "=f"(x), "=f"(y) : "l"(p));
}
__device__ __forceinline__ void fma2(u64 &d, u64 a, u64 b) {
    asm("fma.rn.f32x2 %0, %1, %2, %0;" : "+l"(d) : "l"(a), "l"(b));
}

__device__ __forceinline__ float signf(float x) {
    return (x > 0.f) ? 1.f : ((x < 0.f) ? -1.f : 0.f);
}

extern __shared__ __align__(16) float smem[];

__global__ void __launch_bounds__(256, 2)
draftbot_kernel(const float* __restrict__ X, const float* __restrict__ W,
                float* __restrict__ out)
{
    u64*   Wp  = reinterpret_cast<u64*>(smem);   // [cp][half][ag][t] swizzled, c-pair packed
    float* Wt  = smem + WP_FLOATS;               // [A][C_PAD] c-contiguous (phase 2)
    float* apt = Wt + A_DIM * C_PAD;             // [WARPS][A][APT_PAD] transposed ap

    const int tid = threadIdx.x;

    // ---- stage Wp: c-pair packed + (half, ag, t) swizzle for conflict-free LDS.128 ----
    // reader (lane ag, a = 4ag+q) reads u64 at: cp*32 + (q>>1)*16 + ag*2 + (q&1)
    for (int idx = tid; idx < CP_PAD * 32; idx += 256) {
        int cp = idx >> 5, a = idx & 31;
        int c0 = 2 * cp, c1 = 2 * cp + 1;
        float lo = (c0 < C_DIM) ? W[c0 * A_DIM + a] : 0.f;
        float hi = (c1 < C_DIM) ? W[c1 * A_DIM + a] : 0.f;
        int dst = cp * 32 + ((a >> 1) & 1) * 16 + (a >> 2) * 2 + (a & 1);
        Wp[dst] = pack2(lo, hi);
    }
    // ---- stage W transposed: Wt[a][c] = W[c][a]; coalesced reads ----
    {
        int a = tid & 31;
        for (int c = tid >> 5; c < C_DIM; c += 8)
            Wt[a * C_PAD + c] = W[c * A_DIM + a];
    }
    __syncthreads();

    const int warp = tid >> 5;
    const int lane = tid & 31;
    const int rg   = lane >> 3;   // 0..3 : c-stagger group (quarter-warp)
    const int ag   = lane & 7;    // 0..7 : a-quad group
    const int row0 = blockIdx.x * RPB + warp * RPW;   // warp's first global row

    float* aw = apt + warp * (A_DIM * APT_PAD);

    // ================= Phase 1: ap = cards @ W + 1 =================
    // Lane accumulates ALL 8 rows for a-quad [4ag..4ag+3] over its c-quarter
    // (c4 = 4i+rg). Accumulators are c-parity packed u64. Cross-rg reduction
    // via shfl butterfly at the end.
    {
        const float4* xcards = reinterpret_cast<const float4*>(
            X + (size_t)row0 * XSTR + C_DIM);      // row r at +r*150 float4

        u64 acc[8][4];
        #pragma unroll
        for (int r = 0; r < 8; r++)
            #pragma unroll
            for (int q = 0; q < 4; q++) acc[r][q] = 0ull;

        const u64* wlane = Wp + ag * 2;

        #pragma unroll 1
        for (int i = 0; i < 19; i++) {
            const int c4 = 4 * i + rg;            // 0..75 (75 invalid: rg3@i18)
            const bool ok = (c4 < 75);
            const u64* wp = wlane + (size_t)(2 * c4) * 32;   // cp0 = 2*c4
            // cp0 weights (a = 4ag+q), cp1 at +32
            u64 w00 = wp[0],  w01 = wp[1],  w02 = wp[16], w03 = wp[17];
            u64 w10 = wp[32], w11 = wp[33], w12 = wp[48], w13 = wp[49];

            #pragma unroll
            for (int r = 0; r < 8; r++) {
                float4 v = ok ? xcards[r * 150 + c4]
                              : make_float4(0.f, 0.f, 0.f, 0.f);
                u64 vlo = pack2(v.x, v.y);        // (c even, c odd) of cp0
                u64 vhi = pack2(v.z, v.w);        // cp1
                fma2(acc[r][0], vlo, w00); fma2(acc[r][1], vlo, w01);
                fma2(acc[r][2], vlo, w02); fma2(acc[r][3], vlo, w03);
                fma2(acc[r][0], vhi, w10); fma2(acc[r][1], vhi, w11);
                fma2(acc[r][2], vhi, w12); fma2(acc[r][3], vhi, w13);
            }
        }

        // merge c-parity halves, then butterfly-reduce over rg (lane bits 3,4)
        float s[8][4];
        #pragma unroll
        for (int r = 0; r < 8; r++)
            #pragma unroll
            for (int q = 0; q < 4; q++) {
                float lo, hi; unpack2(acc[r][q], lo, hi);
                s[r][q] = lo + hi;
            }
        #pragma unroll
        for (int r = 0; r < 8; r++)
            #pragma unroll
            for (int q = 0; q < 4; q++) {
                s[r][q] += __shfl_xor_sync(0xffffffffu, s[r][q], 8);
                s[r][q] += __shfl_xor_sync(0xffffffffu, s[r][q], 16);
            }

        // write apt[a][m] = s + 1; lane (rg,ag) writes rows {2rg, 2rg+1}
        #pragma unroll
        for (int q = 0; q < 4; q++)
            #pragma unroll
            for (int e = 0; e < 2; e++) {
                float val = (rg == 0) ? s[0 + e][q]
                          : (rg == 1) ? s[2 + e][q]
                          : (rg == 2) ? s[4 + e][q]
                          :             s[6 + e][q];
                aw[(4 * ag + q) * APT_PAD + 2 * rg + e] = val + 1.f;
            }
    }
    __syncwarp();

    // ================= Phase 2: t = ap @ W^T =================
    // lane owns column-pairs c = 2*lane + 64*j, j = 0..4 (j=4 predicated)
    const bool j4ok = (2 * lane + 256) < C_DIM;   // lanes 0..21

    u64 acc[RPW][5];
    #pragma unroll
    for (int m = 0; m < RPW; m++)
        #pragma unroll
        for (int j = 0; j < 5; j++) acc[m][j] = 0ull;

    #pragma unroll 4
    for (int a = 0; a < A_DIM; a++) {
        const float* ar = aw + a * APT_PAD;
        float4 lo = *reinterpret_cast<const float4*>(ar);      // broadcast
        float4 hi = *reinterpret_cast<const float4*>(ar + 4);  // broadcast
        u64 apd[RPW] = { dup2(lo.x), dup2(lo.y), dup2(lo.z), dup2(lo.w),
                         dup2(hi.x), dup2(hi.y), dup2(hi.z), dup2(hi.w) };

        const float* wr = Wt + a * C_PAD + 2 * lane;
        u64 w0  = *reinterpret_cast<const u64*>(wr);
        u64 w1  = *reinterpret_cast<const u64*>(wr + 64);
        u64 w2v = *reinterpret_cast<const u64*>(wr + 128);
        u64 w3  = *reinterpret_cast<const u64*>(wr + 192);
        u64 w4v = j4ok ? *reinterpret_cast<const u64*>(wr + 256) : 0ull;

        #pragma unroll
        for (int m = 0; m < RPW; m++) {
            fma2(acc[m][0], apd[m], w0);
            fma2(acc[m][1], apd[m], w1);
            fma2(acc[m][2], apd[m], w2v);
            fma2(acc[m][3], apd[m], w3);
            fma2(acc[m][4], apd[m], w4v);
        }
    }

    // ====== Phase 3: scores = options * t; sign-aware log-softmax; store ======
    const int cb = 2 * lane;
    #pragma unroll
    for (int m = 0; m < RPW; m++) {
        const int row = row0 + m;
        const float* optp = X + (size_t)row * XSTR + cb;   // options block
        float v[10];
        #pragma unroll
        for (int j = 0; j < 5; j++) {
            float tx, ty; unpack2(acc[m][j], tx, ty);
            if (j < 4 || j4ok) {
                float2 o = *reinterpret_cast<const float2*>(optp + 64 * j);
                v[2*j]   = o.x * tx;
                v[2*j+1] = o.y * ty;
            } else {
                v[2*j] = 0.f; v[2*j+1] = 0.f;
            }
        }

        // row max (b) over valid columns only
        float mx = -FLT_MAX;
        #pragma unroll
        for (int i = 0; i < 10; i++)
            if (i < 8 || j4ok) mx = fmaxf(mx, v[i]);
        #pragma unroll
        for (int off = 16; off; off >>= 1)
            mx = fmaxf(mx, __shfl_xor_sync(0xffffffffu, mx, off));

        // ssum = sum s * exp(x - b*s)   (s=0 entries contribute exactly 0)
        float ss = 0.f;
        #pragma unroll
        for (int i = 0; i < 10; i++) {
            if (i < 8 || j4ok) {
                float x = v[i];
                float s = signf(x);
                ss += s * __expf(fmaf(-mx, s, x));
            }
        }
        #pragma unroll
        for (int off = 16; off; off >>= 1)
            ss += __shfl_xor_sync(0xffffffffu, ss, off);

        float lse = __logf(ss);

        float* op = out + (size_t)row * C_DIM + cb;
        #pragma unroll
        for (int j = 0; j < 5; j++) {
            if (j < 4 || j4ok) {
                float2 r;
                {
                    float x = v[2*j];   float s = signf(x);
                    r.x = (s != 0.f) ? s * (fmaf(-mx, s, x) - lse) : 0.f;
                }
                {
                    float x = v[2*j+1]; float s = signf(x);
                    r.y = (s != 0.f) ? s * (fmaf(-mx, s, x) - lse) : 0.f;
                }
                *reinterpret_cast<float2*>(op + 64 * j) = r;
            }
        }
    }
}

extern "C" void kernel_launch(void* const* d_in, const int* in_sizes, int n_in,
                              void* d_out, int out_size)
{
    const float* X = (const float*)d_in[0];
    const float* W = (const float*)d_in[1];
    float* out     = (float*)d_out;

    const int rows = in_sizes[0] / XSTR;        // 65536
    const int grid = rows / RPB;                // 1024

    cudaFuncSetAttribute(draftbot_kernel,
                         cudaFuncAttributeMaxDynamicSharedMemorySize, SMEM_BYTES);
    draftbot_kernel<<<grid, 256, SMEM_BYTES>>>(X, W, out);
}